// round 11
// baseline (speedup 1.0000x reference)
#include <cuda_runtime.h>

#define NF 64
#define NH 256
#define NB 8192

typedef unsigned long long u64;

// Per chain-lane widx (0..63 per f), owning 4 consecutive h = [4w, 4w+3]:
//   g_wl[f*64+w] : packed (exp(exu_w)*log2e) for (h0,h1),(h2,h3)
//   g_w2[f*64+w] : packed 2*exp(exu_w)*dense_k, same pairing
//   g_ws[f*64+w] : packed pair-sums (wd0+wd2, wd1+wd3), wd = exp(exu_w)*dense_k
__device__ float4 g_wl[NF * NH / 4];
__device__ float4 g_w2[NF * NH / 4];
__device__ float2 g_ws[NF * NH / 4];
__device__ float g_sumdb;

__global__ void prep_kernel(const float* __restrict__ exu_w,
                            const float* __restrict__ dense_k,
                            const float* __restrict__ dense_b) {
    int i = blockIdx.x * blockDim.x + threadIdx.x;   // 4096 total
    if (i < NF * NH / 4) {
        float4 w = *reinterpret_cast<const float4*>(exu_w + 4 * i);
        float4 k = *reinterpret_cast<const float4*>(dense_k + 4 * i);
        float e0 = expf(w.x), e1 = expf(w.y), e2 = expf(w.z), e3 = expf(w.w);
        const float L2E = 1.4426950408889634f;
        g_wl[i] = make_float4(e0 * L2E, e1 * L2E, e2 * L2E, e3 * L2E);
        float d0 = e0 * k.x, d1 = e1 * k.y, d2 = e2 * k.z, d3 = e3 * k.w;
        g_w2[i] = make_float4(2.f * d0, 2.f * d1, 2.f * d2, 2.f * d3);
        g_ws[i] = make_float2(d0 + d2, d1 + d3);
    }
    if (blockIdx.x == 0 && threadIdx.x < 32) {
        float s = dense_b[threadIdx.x] + dense_b[threadIdx.x + 32];
        #pragma unroll
        for (int o = 16; o > 0; o >>= 1)
            s += __shfl_down_sync(0xffffffffu, s, o);
        if (threadIdx.x == 0) g_sumdb = s;
    }
}

__device__ __forceinline__ u64 mul2(u64 a, u64 b) {
    u64 d; asm("mul.rn.f32x2 %0, %1, %2;" : "=l"(d) : "l"(a), "l"(b)); return d;
}
__device__ __forceinline__ u64 add2(u64 a, u64 b) {
    u64 d; asm("add.rn.f32x2 %0, %1, %2;" : "=l"(d) : "l"(a), "l"(b)); return d;
}
__device__ __forceinline__ u64 fma2(u64 a, u64 b, u64 c) {
    u64 d; asm("fma.rn.f32x2 %0, %1, %2, %3;" : "=l"(d) : "l"(a), "l"(b), "l"(c)); return d;
}
__device__ __forceinline__ u64 pack2(float lo, float hi) {
    u64 d; asm("mov.b64 %0, {%1, %2};" : "=l"(d) : "f"(lo), "f"(hi)); return d;
}
__device__ __forceinline__ float2 unpack2(u64 x) {
    float lo, hi; asm("mov.b64 {%0, %1}, %2;" : "=f"(lo), "=f"(hi) : "l"(x));
    return make_float2(lo, hi);
}

// Fused clamp + ex2 on both packed halves; temporaries scoped to the block so
// ptxas can place them on the halves of the in/out register pairs.
__device__ __forceinline__ u64 ex2pc(u64 a) {
    u64 t;
    asm("{\n\t"
        ".reg .f32 l, h;\n\t"
        "mov.b64 {l, h}, %1;\n\t"
        "min.f32 l, l, 0f41700000;\n\t"   // 15.0f
        "min.f32 h, h, 0f41700000;\n\t"
        "ex2.approx.f32 l, l;\n\t"
        "ex2.approx.f32 h, h;\n\t"
        "mov.b64 %0, {l, h};\n\t"
        "}" : "=l"(t) : "l"(a));
    return t;
}

// ratio = tanh(softplus(x)) = 1 - 2/v, v = t(t+2)+2, t = exp2(arg), arg = d*wl.
// Clamp arg at 15: v <= ~2^30 (finite for the int-seed rcp), ratio rounds to 1.0f.
// Shared reciprocal g ~= -1/(vA*vB): 64-bit magic seed + ONE cubic (Halley) step.
// Per-f contribution per packed lane: ws + g*(2wd0*vB + 2wd2*vA) = ws + g*m.
//
// R11 (on the R9 winner): (1) d staged PRE-DUPLICATED as u64 (d,d) in smem —
// inner loop uses broadcast LDS.64 and drops 8 pack-MOVs per fb-iter plus the
// dm[] register block; (2) fb loop unroll 2 so ptxas overlaps next-iteration
// weight LDGs with current compute (cross-iteration MLP).
__global__ void __launch_bounds__(128, 8)
nam_kernel(const float* __restrict__ X,
           const float* __restrict__ exu_b,
           float* __restrict__ out) {
    const u64 TWO2   = 0x4000000040000000ULL;
    const u64 ONE2   = 0x3F8000003F800000ULL;
    const u64 MAGIC2 = 0xFEF311C3FEF311C3ULL;

    const int tid  = threadIdx.x;
    const int lane = tid & 31;
    const int wid  = tid >> 5;            // 0..3
    const int half = wid & 1;
    const int grp  = wid >> 1;            // 0..1
    const int widx = half * 32 + lane;    // 0..63 within f-row

    __shared__ u64 sdd[4][NF];            // (d,d) duplicated pairs per row,f
    __shared__ float sp[4][2];

    // Prologue: 128 threads compute 256 d-values (2 each), coalesced LDG.
    {
        const int bb = blockIdx.x * 4;    // first batch row of this block
        #pragma unroll
        for (int k = 0; k < 2; ++k) {
            int idx = tid + k * 128;      // 0..255
            int row = idx >> 6;
            int f   = idx & 63;
            float d = X[(bb + row) * NF + f] - exu_b[f];
            sdd[row][f] = pack2(d, d);
        }
    }
    __syncthreads();

    const ulonglong2* wlp = reinterpret_cast<const ulonglong2*>(g_wl) + widx;
    const ulonglong2* w2p = reinterpret_cast<const ulonglong2*>(g_w2) + widx;
    const u64*        wsp = reinterpret_cast<const u64*>(g_ws) + widx;

    u64 acc2[2] = {0ULL, 0ULL};

    #pragma unroll 2
    for (int fb = 0; fb < NF; fb += 4) {
        #pragma unroll
        for (int j = 0; j < 4; ++j) {
            const int f   = fb + j;
            const int idx = f * 64;             // pre-offset pointers carry widx
            ulonglong2 wl = wlp[idx];
            ulonglong2 W  = w2p[idx];
            u64        ws = wsp[idx];
            #pragma unroll
            for (int r = 0; r < 2; ++r) {
                u64 dd = sdd[grp * 2 + r][f];   // broadcast LDS.64, warp-uniform
                u64 tA = ex2pc(mul2(dd, wl.x));
                u64 tB = ex2pc(mul2(dd, wl.y));
                u64 vA = fma2(tA, add2(tA, TWO2), TWO2);
                u64 vB = fma2(tB, add2(tB, TWO2), TWO2);
                u64 P  = mul2(vA, vB);
                u64 g  = MAGIC2 - P;                    // packed seed ~ -1/P
                u64 e  = fma2(P, g, ONE2);              // -> 0
                u64 t  = fma2(e, e, e);                 // e + e^2
                g = fma2(g, t, g);                      // cubic step
                u64 m = fma2(W.x, vB, mul2(W.y, vA));
                acc2[r] = fma2(dd, fma2(m, g, ws), acc2[r]);
            }
        }
    }

    float accs[2];
    #pragma unroll
    for (int r = 0; r < 2; ++r) {
        float2 u = unpack2(acc2[r]);
        float a = u.x + u.y;
        #pragma unroll
        for (int o = 16; o > 0; o >>= 1)
            a += __shfl_down_sync(0xffffffffu, a, o);
        accs[r] = a;
    }

    if (lane == 0) {
        sp[wid][0] = accs[0];
        sp[wid][1] = accs[1];
    }
    __syncthreads();
    if (tid < 4) {
        int g = tid >> 1, r = tid & 1;
        out[blockIdx.x * 4 + g * 2 + r] = sp[2 * g][r] + sp[2 * g + 1][r] + g_sumdb;
    }
}

extern "C" void kernel_launch(void* const* d_in, const int* in_sizes, int n_in,
                              void* d_out, int out_size) {
    const float* X       = (const float*)d_in[0];
    const float* exu_w   = (const float*)d_in[1];
    const float* exu_b   = (const float*)d_in[2];
    const float* dense_k = (const float*)d_in[3];
    const float* dense_b = (const float*)d_in[4];
    float* out = (float*)d_out;

    (void)in_sizes; (void)n_in; (void)out_size;

    prep_kernel<<<(NF * NH / 4 + 255) / 256, 256>>>(exu_w, dense_k, dense_b);
    nam_kernel<<<NB / 4, 128>>>(X, exu_b, out);
}

// round 12
// speedup vs baseline: 1.6294x; 1.6294x over previous
#include <cuda_runtime.h>

#define NF 64
#define NH 256
#define NB 8192

typedef unsigned long long u64;

// Per chain-lane widx (0..63 per f), owning 4 consecutive h = [4w, 4w+3]:
//   g_wl[f*64+w] : packed (exp(exu_w)*log2e) for (h0,h1),(h2,h3)
//   g_w2[f*64+w] : packed 2*exp(exu_w)*dense_k, same pairing
//   g_ws[f*64+w] : packed pair-sums (wd0+wd2, wd1+wd3), wd = exp(exu_w)*dense_k
__device__ float4 g_wl[NF * NH / 4];
__device__ float4 g_w2[NF * NH / 4];
__device__ float2 g_ws[NF * NH / 4];
__device__ float g_sumdb;

__global__ void prep_kernel(const float* __restrict__ exu_w,
                            const float* __restrict__ dense_k,
                            const float* __restrict__ dense_b) {
    int i = blockIdx.x * blockDim.x + threadIdx.x;   // 4096 total
    if (i < NF * NH / 4) {
        float4 w = *reinterpret_cast<const float4*>(exu_w + 4 * i);
        float4 k = *reinterpret_cast<const float4*>(dense_k + 4 * i);
        float e0 = expf(w.x), e1 = expf(w.y), e2 = expf(w.z), e3 = expf(w.w);
        const float L2E = 1.4426950408889634f;
        g_wl[i] = make_float4(e0 * L2E, e1 * L2E, e2 * L2E, e3 * L2E);
        float d0 = e0 * k.x, d1 = e1 * k.y, d2 = e2 * k.z, d3 = e3 * k.w;
        g_w2[i] = make_float4(2.f * d0, 2.f * d1, 2.f * d2, 2.f * d3);
        g_ws[i] = make_float2(d0 + d2, d1 + d3);
    }
    if (blockIdx.x == 0 && threadIdx.x < 32) {
        float s = dense_b[threadIdx.x] + dense_b[threadIdx.x + 32];
        #pragma unroll
        for (int o = 16; o > 0; o >>= 1)
            s += __shfl_down_sync(0xffffffffu, s, o);
        if (threadIdx.x == 0) g_sumdb = s;
    }
}

__device__ __forceinline__ u64 mul2(u64 a, u64 b) {
    u64 d; asm("mul.rn.f32x2 %0, %1, %2;" : "=l"(d) : "l"(a), "l"(b)); return d;
}
__device__ __forceinline__ u64 add2(u64 a, u64 b) {
    u64 d; asm("add.rn.f32x2 %0, %1, %2;" : "=l"(d) : "l"(a), "l"(b)); return d;
}
__device__ __forceinline__ u64 fma2(u64 a, u64 b, u64 c) {
    u64 d; asm("fma.rn.f32x2 %0, %1, %2, %3;" : "=l"(d) : "l"(a), "l"(b), "l"(c)); return d;
}
__device__ __forceinline__ u64 pack2(float lo, float hi) {
    u64 d; asm("mov.b64 %0, {%1, %2};" : "=l"(d) : "f"(lo), "f"(hi)); return d;
}
__device__ __forceinline__ float2 unpack2(u64 x) {
    float lo, hi; asm("mov.b64 {%0, %1}, %2;" : "=f"(lo), "=f"(hi) : "l"(x));
    return make_float2(lo, hi);
}

// Fused clamp + ex2 on both packed halves; temporaries scoped to the block so
// ptxas can place them on the halves of the in/out register pairs.
__device__ __forceinline__ u64 ex2pc(u64 a) {
    u64 t;
    asm("{\n\t"
        ".reg .f32 l, h;\n\t"
        "mov.b64 {l, h}, %1;\n\t"
        "min.f32 l, l, 0f41700000;\n\t"   // 15.0f
        "min.f32 h, h, 0f41700000;\n\t"
        "ex2.approx.f32 l, l;\n\t"
        "ex2.approx.f32 h, h;\n\t"
        "mov.b64 %0, {l, h};\n\t"
        "}" : "=l"(t) : "l"(a));
    return t;
}

// ratio = tanh(softplus(x)) = 1 - 2/v, v = t(t+2)+2, t = exp2(arg), arg = d*wl.
// Clamp arg at 15: v <= ~2^30 (finite for the int-seed rcp), ratio rounds to 1.0f.
// Shared reciprocal g ~= -1/(vA*vB): 64-bit magic seed + ONE cubic (Halley) step.
// Per-f contribution per packed lane: ws + g*(2wd0*vB + 2wd2*vA) = ws + g*m.
//
// R12 = R9 winner + ONE isolated change from R11: d staged pre-duplicated as
// u64 (d,d) in smem (kills 8 pack-MOVs per fb-iter). fb loop stays unroll 1 —
// R11 proved unroll 2 batches ~12 LDG.128/warp in flight and thrashes the L1
// weight working set out to L2/HBM (DRAM 0.5% -> 5.6%).
__global__ void __launch_bounds__(128, 8)
nam_kernel(const float* __restrict__ X,
           const float* __restrict__ exu_b,
           float* __restrict__ out) {
    const u64 TWO2   = 0x4000000040000000ULL;
    const u64 ONE2   = 0x3F8000003F800000ULL;
    const u64 MAGIC2 = 0xFEF311C3FEF311C3ULL;

    const int tid  = threadIdx.x;
    const int lane = tid & 31;
    const int wid  = tid >> 5;            // 0..3
    const int half = wid & 1;
    const int grp  = wid >> 1;            // 0..1
    const int widx = half * 32 + lane;    // 0..63 within f-row

    __shared__ u64 sdd[4][NF];            // (d,d) duplicated pairs per row,f
    __shared__ float sp[4][2];

    // Prologue: 128 threads compute 256 d-values (2 each), coalesced LDG.
    {
        const int bb = blockIdx.x * 4;    // first batch row of this block
        #pragma unroll
        for (int k = 0; k < 2; ++k) {
            int idx = tid + k * 128;      // 0..255
            int row = idx >> 6;
            int f   = idx & 63;
            float d = X[(bb + row) * NF + f] - exu_b[f];
            sdd[row][f] = pack2(d, d);
        }
    }
    __syncthreads();

    const ulonglong2* wlp = reinterpret_cast<const ulonglong2*>(g_wl) + widx;
    const ulonglong2* w2p = reinterpret_cast<const ulonglong2*>(g_w2) + widx;
    const u64*        wsp = reinterpret_cast<const u64*>(g_ws) + widx;

    u64 acc2[2] = {0ULL, 0ULL};

    #pragma unroll 1
    for (int fb = 0; fb < NF; fb += 4) {
        #pragma unroll
        for (int j = 0; j < 4; ++j) {
            const int f   = fb + j;
            const int idx = f * 64;             // pre-offset pointers carry widx
            ulonglong2 wl = wlp[idx];
            ulonglong2 W  = w2p[idx];
            u64        ws = wsp[idx];
            #pragma unroll
            for (int r = 0; r < 2; ++r) {
                u64 dd = sdd[grp * 2 + r][f];   // broadcast LDS.64, warp-uniform
                u64 tA = ex2pc(mul2(dd, wl.x));
                u64 tB = ex2pc(mul2(dd, wl.y));
                u64 vA = fma2(tA, add2(tA, TWO2), TWO2);
                u64 vB = fma2(tB, add2(tB, TWO2), TWO2);
                u64 P  = mul2(vA, vB);
                u64 g  = MAGIC2 - P;                    // packed seed ~ -1/P
                u64 e  = fma2(P, g, ONE2);              // -> 0
                u64 t  = fma2(e, e, e);                 // e + e^2
                g = fma2(g, t, g);                      // cubic step
                u64 m = fma2(W.x, vB, mul2(W.y, vA));
                acc2[r] = fma2(dd, fma2(m, g, ws), acc2[r]);
            }
        }
    }

    float accs[2];
    #pragma unroll
    for (int r = 0; r < 2; ++r) {
        float2 u = unpack2(acc2[r]);
        float a = u.x + u.y;
        #pragma unroll
        for (int o = 16; o > 0; o >>= 1)
            a += __shfl_down_sync(0xffffffffu, a, o);
        accs[r] = a;
    }

    if (lane == 0) {
        sp[wid][0] = accs[0];
        sp[wid][1] = accs[1];
    }
    __syncthreads();
    if (tid < 4) {
        int g = tid >> 1, r = tid & 1;
        out[blockIdx.x * 4 + g * 2 + r] = sp[2 * g][r] + sp[2 * g + 1][r] + g_sumdb;
    }
}

extern "C" void kernel_launch(void* const* d_in, const int* in_sizes, int n_in,
                              void* d_out, int out_size) {
    const float* X       = (const float*)d_in[0];
    const float* exu_w   = (const float*)d_in[1];
    const float* exu_b   = (const float*)d_in[2];
    const float* dense_k = (const float*)d_in[3];
    const float* dense_b = (const float*)d_in[4];
    float* out = (float*)d_out;

    (void)in_sizes; (void)n_in; (void)out_size;

    prep_kernel<<<(NF * NH / 4 + 255) / 256, 256>>>(exu_w, dense_k, dense_b);
    nam_kernel<<<NB / 4, 128>>>(X, exu_b, out);
}

// round 13
// speedup vs baseline: 1.7536x; 1.0762x over previous
#include <cuda_runtime.h>

#define NF 64
#define NH 256
#define NB 8192

typedef unsigned long long u64;

// Per chain-lane widx (0..63 per f), owning 4 consecutive h = [4w, 4w+3]:
//   g_wl[f*64+w] : packed (exp(exu_w)*log2e) for (h0,h1),(h2,h3)
//   g_w2[f*64+w] : packed 2*exp(exu_w)*dense_k, same pairing
//   g_ws[f*64+w] : packed pair-sums (wd0+wd2, wd1+wd3), wd = exp(exu_w)*dense_k
__device__ float4 g_wl[NF * NH / 4];
__device__ float4 g_w2[NF * NH / 4];
__device__ float2 g_ws[NF * NH / 4];
__device__ float g_sumdb;

__global__ void prep_kernel(const float* __restrict__ exu_w,
                            const float* __restrict__ dense_k,
                            const float* __restrict__ dense_b) {
    int i = blockIdx.x * blockDim.x + threadIdx.x;   // 4096 total
    if (i < NF * NH / 4) {
        float4 w = *reinterpret_cast<const float4*>(exu_w + 4 * i);
        float4 k = *reinterpret_cast<const float4*>(dense_k + 4 * i);
        float e0 = expf(w.x), e1 = expf(w.y), e2 = expf(w.z), e3 = expf(w.w);
        const float L2E = 1.4426950408889634f;
        g_wl[i] = make_float4(e0 * L2E, e1 * L2E, e2 * L2E, e3 * L2E);
        float d0 = e0 * k.x, d1 = e1 * k.y, d2 = e2 * k.z, d3 = e3 * k.w;
        g_w2[i] = make_float4(2.f * d0, 2.f * d1, 2.f * d2, 2.f * d3);
        g_ws[i] = make_float2(d0 + d2, d1 + d3);
    }
    if (blockIdx.x == 0 && threadIdx.x < 32) {
        float s = dense_b[threadIdx.x] + dense_b[threadIdx.x + 32];
        #pragma unroll
        for (int o = 16; o > 0; o >>= 1)
            s += __shfl_down_sync(0xffffffffu, s, o);
        if (threadIdx.x == 0) g_sumdb = s;
    }
}

__device__ __forceinline__ u64 mul2(u64 a, u64 b) {
    u64 d; asm("mul.rn.f32x2 %0, %1, %2;" : "=l"(d) : "l"(a), "l"(b)); return d;
}
__device__ __forceinline__ u64 add2(u64 a, u64 b) {
    u64 d; asm("add.rn.f32x2 %0, %1, %2;" : "=l"(d) : "l"(a), "l"(b)); return d;
}
__device__ __forceinline__ u64 fma2(u64 a, u64 b, u64 c) {
    u64 d; asm("fma.rn.f32x2 %0, %1, %2, %3;" : "=l"(d) : "l"(a), "l"(b), "l"(c)); return d;
}
__device__ __forceinline__ u64 pack2(float lo, float hi) {
    u64 d; asm("mov.b64 %0, {%1, %2};" : "=l"(d) : "f"(lo), "f"(hi)); return d;
}
__device__ __forceinline__ float2 unpack2(u64 x) {
    float lo, hi; asm("mov.b64 {%0, %1}, %2;" : "=f"(lo), "=f"(hi) : "l"(x));
    return make_float2(lo, hi);
}

// Fused clamp + ex2 on both packed halves; temporaries scoped to the block so
// ptxas can place them on the halves of the in/out register pairs.
__device__ __forceinline__ u64 ex2pc(u64 a) {
    u64 t;
    asm("{\n\t"
        ".reg .f32 l, h;\n\t"
        "mov.b64 {l, h}, %1;\n\t"
        "min.f32 l, l, 0f41700000;\n\t"   // 15.0f
        "min.f32 h, h, 0f41700000;\n\t"
        "ex2.approx.f32 l, l;\n\t"
        "ex2.approx.f32 h, h;\n\t"
        "mov.b64 %0, {l, h};\n\t"
        "}" : "=l"(t) : "l"(a));
    return t;
}

// ratio = tanh(softplus(x)) = 1 - 2/v, v = t(t+2)+2, t = exp2(arg), arg = d*wl.
// Clamp arg at 15: v <= ~2^30 (finite for the int-seed rcp), ratio rounds to 1.0f.
// Shared reciprocal g ~= -1/(vA*vB): 64-bit magic seed + ONE cubic (Halley) step.
// Per-f contribution per packed lane: ws + g*(2wd0*vB + 2wd2*vA) = ws + g*m.
//
// R13 = R9 winner with ONE variable changed: __launch_bounds__(128, 6).
// The j-loop is fully unrolled so ptxas already sees 8 independent chains per
// fb body; at 64 regs it can only keep ~2.5 in flight (issue 69%, latency
// bound). 6 CTAs/SM frees ~85 regs/thread for deeper chain overlap while
// still leaving 24 warps/SM for arbiter coverage. R12 confirmed chain-head
// latency dominates, so d stays in registers (LDS.128 at fb head only).
__global__ void __launch_bounds__(128, 6)
nam_kernel(const float* __restrict__ X,
           const float* __restrict__ exu_b,
           float* __restrict__ out) {
    const u64 TWO2   = 0x4000000040000000ULL;
    const u64 ONE2   = 0x3F8000003F800000ULL;
    const u64 MAGIC2 = 0xFEF311C3FEF311C3ULL;

    const int tid  = threadIdx.x;
    const int lane = tid & 31;
    const int wid  = tid >> 5;            // 0..3
    const int half = wid & 1;
    const int grp  = wid >> 1;            // 0..1
    const int widx = half * 32 + lane;    // 0..63 within f-row

    __shared__ float sd[4][NF];           // d = X - exu_b for the block's 4 rows
    __shared__ float sp[4][2];

    // Prologue: 128 threads compute 256 d-values (2 each), coalesced LDG.
    {
        const int bb = blockIdx.x * 4;    // first batch row of this block
        #pragma unroll
        for (int k = 0; k < 2; ++k) {
            int idx = tid + k * 128;      // 0..255
            int row = idx >> 6;
            int f   = idx & 63;
            sd[row][f] = X[(bb + row) * NF + f] - exu_b[f];
        }
    }
    __syncthreads();

    const ulonglong2* wlp = reinterpret_cast<const ulonglong2*>(g_wl) + widx;
    const ulonglong2* w2p = reinterpret_cast<const ulonglong2*>(g_w2) + widx;
    const u64*        wsp = reinterpret_cast<const u64*>(g_ws) + widx;

    u64 acc2[2] = {0ULL, 0ULL};

    #pragma unroll 1
    for (int fb = 0; fb < NF; fb += 4) {
        // Broadcast LDS.128 (warp-uniform address, conflict-free, 29cyc)
        float4 d0v = *reinterpret_cast<const float4*>(&sd[grp * 2 + 0][fb]);
        float4 d1v = *reinterpret_cast<const float4*>(&sd[grp * 2 + 1][fb]);
        float dm[2][4] = {{d0v.x, d0v.y, d0v.z, d0v.w},
                          {d1v.x, d1v.y, d1v.z, d1v.w}};

        #pragma unroll
        for (int j = 0; j < 4; ++j) {
            const int idx = (fb + j) * 64;      // pre-offset pointers carry widx
            ulonglong2 wl = wlp[idx];
            ulonglong2 W  = w2p[idx];
            u64        ws = wsp[idx];
            #pragma unroll
            for (int r = 0; r < 2; ++r) {
                float d = dm[r][j];
                u64 dd = pack2(d, d);
                u64 tA = ex2pc(mul2(dd, wl.x));
                u64 tB = ex2pc(mul2(dd, wl.y));
                u64 vA = fma2(tA, add2(tA, TWO2), TWO2);
                u64 vB = fma2(tB, add2(tB, TWO2), TWO2);
                u64 P  = mul2(vA, vB);
                u64 g  = MAGIC2 - P;                    // packed seed ~ -1/P
                u64 e  = fma2(P, g, ONE2);              // -> 0
                u64 t  = fma2(e, e, e);                 // e + e^2
                g = fma2(g, t, g);                      // cubic step
                u64 m = fma2(W.x, vB, mul2(W.y, vA));
                acc2[r] = fma2(dd, fma2(m, g, ws), acc2[r]);
            }
        }
    }

    float accs[2];
    #pragma unroll
    for (int r = 0; r < 2; ++r) {
        float2 u = unpack2(acc2[r]);
        float a = u.x + u.y;
        #pragma unroll
        for (int o = 16; o > 0; o >>= 1)
            a += __shfl_down_sync(0xffffffffu, a, o);
        accs[r] = a;
    }

    if (lane == 0) {
        sp[wid][0] = accs[0];
        sp[wid][1] = accs[1];
    }
    __syncthreads();
    if (tid < 4) {
        int g = tid >> 1, r = tid & 1;
        out[blockIdx.x * 4 + g * 2 + r] = sp[2 * g][r] + sp[2 * g + 1][r] + g_sumdb;
    }
}

extern "C" void kernel_launch(void* const* d_in, const int* in_sizes, int n_in,
                              void* d_out, int out_size) {
    const float* X       = (const float*)d_in[0];
    const float* exu_w   = (const float*)d_in[1];
    const float* exu_b   = (const float*)d_in[2];
    const float* dense_k = (const float*)d_in[3];
    const float* dense_b = (const float*)d_in[4];
    float* out = (float*)d_out;

    (void)in_sizes; (void)n_in; (void)out_size;

    prep_kernel<<<(NF * NH / 4 + 255) / 256, 256>>>(exu_w, dense_k, dense_b);
    nam_kernel<<<NB / 4, 128>>>(X, exu_b, out);
}

// round 14
// speedup vs baseline: 1.7546x; 1.0006x over previous
#include <cuda_runtime.h>

#define NF 64
#define NH 256
#define NB 8192

typedef unsigned long long u64;

// Per chain-lane widx (0..63 per f), owning 4 consecutive h = [4w, 4w+3]:
//   g_wl[f*64+w] : packed (exp(exu_w)*log2e) for (h0,h1),(h2,h3)
//   g_w2[f*64+w] : packed 2*exp(exu_w)*dense_k, same pairing
//   g_ws[f*64+w] : packed pair-sums (wd0+wd2, wd1+wd3), wd = exp(exu_w)*dense_k
__device__ float4 g_wl[NF * NH / 4];
__device__ float4 g_w2[NF * NH / 4];
__device__ float2 g_ws[NF * NH / 4];
__device__ float g_sumdb;

__global__ void prep_kernel(const float* __restrict__ exu_w,
                            const float* __restrict__ dense_k,
                            const float* __restrict__ dense_b) {
    int i = blockIdx.x * blockDim.x + threadIdx.x;   // 4096 total
    if (i < NF * NH / 4) {
        float4 w = *reinterpret_cast<const float4*>(exu_w + 4 * i);
        float4 k = *reinterpret_cast<const float4*>(dense_k + 4 * i);
        float e0 = expf(w.x), e1 = expf(w.y), e2 = expf(w.z), e3 = expf(w.w);
        const float L2E = 1.4426950408889634f;
        g_wl[i] = make_float4(e0 * L2E, e1 * L2E, e2 * L2E, e3 * L2E);
        float d0 = e0 * k.x, d1 = e1 * k.y, d2 = e2 * k.z, d3 = e3 * k.w;
        g_w2[i] = make_float4(2.f * d0, 2.f * d1, 2.f * d2, 2.f * d3);
        g_ws[i] = make_float2(d0 + d2, d1 + d3);
    }
    if (blockIdx.x == 0 && threadIdx.x < 32) {
        float s = dense_b[threadIdx.x] + dense_b[threadIdx.x + 32];
        #pragma unroll
        for (int o = 16; o > 0; o >>= 1)
            s += __shfl_down_sync(0xffffffffu, s, o);
        if (threadIdx.x == 0) g_sumdb = s;
    }
}

__device__ __forceinline__ u64 mul2(u64 a, u64 b) {
    u64 d; asm("mul.rn.f32x2 %0, %1, %2;" : "=l"(d) : "l"(a), "l"(b)); return d;
}
__device__ __forceinline__ u64 add2(u64 a, u64 b) {
    u64 d; asm("add.rn.f32x2 %0, %1, %2;" : "=l"(d) : "l"(a), "l"(b)); return d;
}
__device__ __forceinline__ u64 fma2(u64 a, u64 b, u64 c) {
    u64 d; asm("fma.rn.f32x2 %0, %1, %2, %3;" : "=l"(d) : "l"(a), "l"(b), "l"(c)); return d;
}
__device__ __forceinline__ u64 pack2(float lo, float hi) {
    u64 d; asm("mov.b64 %0, {%1, %2};" : "=l"(d) : "f"(lo), "f"(hi)); return d;
}
__device__ __forceinline__ float2 unpack2(u64 x) {
    float lo, hi; asm("mov.b64 {%0, %1}, %2;" : "=f"(lo), "=f"(hi) : "l"(x));
    return make_float2(lo, hi);
}

// Fused clamp + ex2 on both packed halves; temporaries scoped to the block so
// ptxas can place them on the halves of the in/out register pairs.
__device__ __forceinline__ u64 ex2pc(u64 a) {
    u64 t;
    asm("{\n\t"
        ".reg .f32 l, h;\n\t"
        "mov.b64 {l, h}, %1;\n\t"
        "min.f32 l, l, 0f41700000;\n\t"   // 15.0f
        "min.f32 h, h, 0f41700000;\n\t"
        "ex2.approx.f32 l, l;\n\t"
        "ex2.approx.f32 h, h;\n\t"
        "mov.b64 %0, {l, h};\n\t"
        "}" : "=l"(t) : "l"(a));
    return t;
}

// ratio = tanh(softplus(x)) = 1 - 2/v, v = t(t+2)+2, t = exp2(arg), arg = d*wl.
// Clamp arg at 15: v <= ~2^30 (finite for the int-seed rcp), ratio rounds to 1.0f.
// Shared reciprocal g ~= -1/(vA*vB): 64-bit magic seed + ONE cubic (Halley) step.
// Per-f contribution per packed lane: ws + g*(2wd0*vB + 2wd2*vA) = ws + g*m.
//
// R14 = R13 champion with the occupancy hint escalated one step: (128, 5).
// Dose-response on the confirmed ILP-over-occupancy lever (R13: 78 regs,
// occ 32.6%, issue 71.8% beat 64-reg/40%-occ). ~102 regs lets ptxas keep ~4
// chains in flight per warp instead of ~3; 20 warps/SM (5/SMSP) remains
// above the arbiter-coverage cliff if ILP substitutes for warp parallelism.
__global__ void __launch_bounds__(128, 5)
nam_kernel(const float* __restrict__ X,
           const float* __restrict__ exu_b,
           float* __restrict__ out) {
    const u64 TWO2   = 0x4000000040000000ULL;
    const u64 ONE2   = 0x3F8000003F800000ULL;
    const u64 MAGIC2 = 0xFEF311C3FEF311C3ULL;

    const int tid  = threadIdx.x;
    const int lane = tid & 31;
    const int wid  = tid >> 5;            // 0..3
    const int half = wid & 1;
    const int grp  = wid >> 1;            // 0..1
    const int widx = half * 32 + lane;    // 0..63 within f-row

    __shared__ float sd[4][NF];           // d = X - exu_b for the block's 4 rows
    __shared__ float sp[4][2];

    // Prologue: 128 threads compute 256 d-values (2 each), coalesced LDG.
    {
        const int bb = blockIdx.x * 4;    // first batch row of this block
        #pragma unroll
        for (int k = 0; k < 2; ++k) {
            int idx = tid + k * 128;      // 0..255
            int row = idx >> 6;
            int f   = idx & 63;
            sd[row][f] = X[(bb + row) * NF + f] - exu_b[f];
        }
    }
    __syncthreads();

    const ulonglong2* wlp = reinterpret_cast<const ulonglong2*>(g_wl) + widx;
    const ulonglong2* w2p = reinterpret_cast<const ulonglong2*>(g_w2) + widx;
    const u64*        wsp = reinterpret_cast<const u64*>(g_ws) + widx;

    u64 acc2[2] = {0ULL, 0ULL};

    #pragma unroll 1
    for (int fb = 0; fb < NF; fb += 4) {
        // Broadcast LDS.128 (warp-uniform address, conflict-free, 29cyc)
        float4 d0v = *reinterpret_cast<const float4*>(&sd[grp * 2 + 0][fb]);
        float4 d1v = *reinterpret_cast<const float4*>(&sd[grp * 2 + 1][fb]);
        float dm[2][4] = {{d0v.x, d0v.y, d0v.z, d0v.w},
                          {d1v.x, d1v.y, d1v.z, d1v.w}};

        #pragma unroll
        for (int j = 0; j < 4; ++j) {
            const int idx = (fb + j) * 64;      // pre-offset pointers carry widx
            ulonglong2 wl = wlp[idx];
            ulonglong2 W  = w2p[idx];
            u64        ws = wsp[idx];
            #pragma unroll
            for (int r = 0; r < 2; ++r) {
                float d = dm[r][j];
                u64 dd = pack2(d, d);
                u64 tA = ex2pc(mul2(dd, wl.x));
                u64 tB = ex2pc(mul2(dd, wl.y));
                u64 vA = fma2(tA, add2(tA, TWO2), TWO2);
                u64 vB = fma2(tB, add2(tB, TWO2), TWO2);
                u64 P  = mul2(vA, vB);
                u64 g  = MAGIC2 - P;                    // packed seed ~ -1/P
                u64 e  = fma2(P, g, ONE2);              // -> 0
                u64 t  = fma2(e, e, e);                 // e + e^2
                g = fma2(g, t, g);                      // cubic step
                u64 m = fma2(W.x, vB, mul2(W.y, vA));
                acc2[r] = fma2(dd, fma2(m, g, ws), acc2[r]);
            }
        }
    }

    float accs[2];
    #pragma unroll
    for (int r = 0; r < 2; ++r) {
        float2 u = unpack2(acc2[r]);
        float a = u.x + u.y;
        #pragma unroll
        for (int o = 16; o > 0; o >>= 1)
            a += __shfl_down_sync(0xffffffffu, a, o);
        accs[r] = a;
    }

    if (lane == 0) {
        sp[wid][0] = accs[0];
        sp[wid][1] = accs[1];
    }
    __syncthreads();
    if (tid < 4) {
        int g = tid >> 1, r = tid & 1;
        out[blockIdx.x * 4 + g * 2 + r] = sp[2 * g][r] + sp[2 * g + 1][r] + g_sumdb;
    }
}

extern "C" void kernel_launch(void* const* d_in, const int* in_sizes, int n_in,
                              void* d_out, int out_size) {
    const float* X       = (const float*)d_in[0];
    const float* exu_w   = (const float*)d_in[1];
    const float* exu_b   = (const float*)d_in[2];
    const float* dense_k = (const float*)d_in[3];
    const float* dense_b = (const float*)d_in[4];
    float* out = (float*)d_out;

    (void)in_sizes; (void)n_in; (void)out_size;

    prep_kernel<<<(NF * NH / 4 + 255) / 256, 256>>>(exu_w, dense_k, dense_b);
    nam_kernel<<<NB / 4, 128>>>(X, exu_b, out);
}